// round 1
// baseline (speedup 1.0000x reference)
#include <cuda_runtime.h>
#include <math.h>

#define NDIMS 3
#define HN    256          // H
#define FN    16           // F
#define MTOT  65536
#define TCOND 100

// conditionals c[n][f] = 1/trapz(relu(series(t)))
__device__ float g_c[NDIMS][FN];

// ---------------- packed f32x2 helpers ----------------
__device__ __forceinline__ unsigned long long pk2(float lo, float hi) {
    unsigned long long r;
    asm("mov.b64 %0, {%1, %2};" : "=l"(r) : "f"(lo), "f"(hi));
    return r;
}
__device__ __forceinline__ void upk2(unsigned long long v, float& lo, float& hi) {
    asm("mov.b64 {%0, %1}, %2;" : "=f"(lo), "=f"(hi) : "l"(v));
}
__device__ __forceinline__ unsigned long long fma2(unsigned long long a,
                                                   unsigned long long b,
                                                   unsigned long long c) {
    unsigned long long d;
    asm("fma.rn.f32x2 %0, %1, %2, %3;" : "=l"(d) : "l"(a), "l"(b), "l"(c));
    return d;
}
__device__ __forceinline__ unsigned long long mul2(unsigned long long a,
                                                   unsigned long long b) {
    unsigned long long d;
    asm("mul.rn.f32x2 %0, %1, %2;" : "=l"(d) : "l"(a), "l"(b));
    return d;
}

// ---------------- kernel 1: conditionals ----------------
// grid = NDIMS, block = 128 (threads 0..99 handle t-points)
__global__ void cond_kernel(const float* __restrict__ fr,
                            const float* __restrict__ fi) {
    __shared__ float sA[HN][FN];   // 2*fr reversed
    __shared__ float sB[HN][FN];   // -2*fi reversed
    __shared__ float integ[FN];
    const int n = blockIdx.x;
    const int tid = threadIdx.x;

    for (int idx = tid; idx < HN * FN; idx += blockDim.x) {
        int f = idx & (FN - 1);
        int jm1 = idx >> 4;               // j-1, j = 1..256
        int src = (n * HN + (HN - 1 - jm1)) * FN + f;
        sA[jm1][f] =  2.0f * fr[src];
        sB[jm1][f] = -2.0f * fi[src];
    }
    if (tid < FN) integ[tid] = 0.0f;
    __syncthreads();

    if (tid < TCOND) {
        const float dt = 0.99f / 99.0f;   // == 0.01
        float t = 0.01f + dt * (float)tid;
        float c1, s1;
        sincospif(2.0f * t, &s1, &c1);
        float acc[FN];
#pragma unroll
        for (int f = 0; f < FN; f++) acc[f] = 1.0f;
        float cj = c1, sj = s1;
        for (int j = 0; j < HN; j++) {
#pragma unroll
            for (int f = 0; f < FN; f++)
                acc[f] += cj * sA[j][f] + sj * sB[j][f];
            float cn = fmaf(cj, c1, -sj * s1);
            float sn = fmaf(cj, s1,  sj * c1);
            cj = cn; sj = sn;
        }
        float w = (tid == 0 || tid == TCOND - 1) ? 0.5f * dt : dt;
#pragma unroll
        for (int f = 0; f < FN; f++)
            atomicAdd(&integ[f], w * fmaxf(acc[f], 0.0f));
    }
    __syncthreads();
    if (tid < FN) g_c[n][tid] = 1.0f / integ[tid];
}

// ---------------- kernel 2: main ----------------
// grid = 256, block = 256  -> one thread per m
// dynamic smem: sA[3][256][16], sB[3][256][16] (prescaled by 2*c), sC[3][16], sLam[16]
#define SMEM_FLOATS (NDIMS * HN * FN * 2 + NDIMS * FN + FN)

__global__ void __launch_bounds__(256, 2)
main_kernel(const float* __restrict__ x,
            const float* __restrict__ fr,
            const float* __restrict__ fi,
            const float* __restrict__ lam,
            float* __restrict__ out) {
    extern __shared__ float smem[];
    float* sA   = smem;                          // 12288
    float* sB   = smem + NDIMS * HN * FN;        // 12288
    float* sC   = smem + 2 * NDIMS * HN * FN;    // 48
    float* sLam = sC + NDIMS * FN;               // 16

    const int tid = threadIdx.x;

    // fill factor tables (reversed in j, prescaled by 2*c[n][f])
    for (int idx = tid; idx < NDIMS * HN * FN; idx += blockDim.x) {
        int f   = idx & (FN - 1);
        int jm1 = (idx >> 4) & (HN - 1);
        int n   = idx >> 12;
        float c = g_c[n][f];
        int src = (n * HN + (HN - 1 - jm1)) * FN + f;
        sA[idx] =  2.0f * c * fr[src];
        sB[idx] = -2.0f * c * fi[src];
    }
    if (tid < NDIMS * FN) sC[tid] = ((const float*)g_c)[tid];
    if (tid < FN)         sLam[tid] = lam[tid];
    __syncthreads();

    const int m = blockIdx.x * blockDim.x + tid;
    const float x0 = x[m * 3 + 0];
    const float x1 = x[m * 3 + 1];
    const float x2 = x[m * 3 + 2];

    float prod[FN];
#pragma unroll
    for (int f = 0; f < FN; f++) prod[f] = 1.0f;

#pragma unroll
    for (int n = 0; n < NDIMS; n++) {
        const float xn = (n == 0) ? x0 : (n == 1) ? x1 : x2;
        float c1, s1;
        sincospif(2.0f * xn, &s1, &c1);
        const unsigned long long K1 = pk2(c1, s1);    // (c1, s1)
        const unsigned long long K2 = pk2(-s1, c1);   // (-s1, c1)

        const ulonglong2* An = (const ulonglong2*)(sA + n * HN * FN);
        const ulonglong2* Bn = (const ulonglong2*)(sB + n * HN * FN);
        const unsigned long long* c0 = (const unsigned long long*)(sC + n * FN);

        unsigned long long acc[8];
#pragma unroll
        for (int p = 0; p < 8; p++) acc[p] = c0[p];   // init with c[n][f]

        unsigned long long cs = K1;                   // (cos 2πx, sin 2πx), j=1
#pragma unroll 2
        for (int j = 0; j < HN; j++) {
            float cj, sj;
            upk2(cs, cj, sj);
            unsigned long long cc = pk2(cj, cj);
            unsigned long long ss = pk2(sj, sj);

            ulonglong2 a0 = An[4 * j + 0];
            ulonglong2 a1 = An[4 * j + 1];
            ulonglong2 a2 = An[4 * j + 2];
            ulonglong2 a3 = An[4 * j + 3];
            ulonglong2 b0 = Bn[4 * j + 0];
            ulonglong2 b1 = Bn[4 * j + 1];
            ulonglong2 b2 = Bn[4 * j + 2];
            ulonglong2 b3 = Bn[4 * j + 3];

            acc[0] = fma2(cc, a0.x, acc[0]);
            acc[1] = fma2(cc, a0.y, acc[1]);
            acc[2] = fma2(cc, a1.x, acc[2]);
            acc[3] = fma2(cc, a1.y, acc[3]);
            acc[4] = fma2(cc, a2.x, acc[4]);
            acc[5] = fma2(cc, a2.y, acc[5]);
            acc[6] = fma2(cc, a3.x, acc[6]);
            acc[7] = fma2(cc, a3.y, acc[7]);
            acc[0] = fma2(ss, b0.x, acc[0]);
            acc[1] = fma2(ss, b0.y, acc[1]);
            acc[2] = fma2(ss, b1.x, acc[2]);
            acc[3] = fma2(ss, b1.y, acc[3]);
            acc[4] = fma2(ss, b2.x, acc[4]);
            acc[5] = fma2(ss, b2.y, acc[5]);
            acc[6] = fma2(ss, b3.x, acc[6]);
            acc[7] = fma2(ss, b3.y, acc[7]);

            // rotate: (c,s) <- (c*c1 - s*s1, c*s1 + s*c1)
            cs = fma2(cc, K1, mul2(ss, K2));
        }

        // relu & multiply into product
#pragma unroll
        for (int p = 0; p < 8; p++) {
            float lo, hi;
            upk2(acc[p], lo, hi);
            prod[2 * p + 0] *= fmaxf(lo, 0.0f);
            prod[2 * p + 1] *= fmaxf(hi, 0.0f);
        }
    }

    float s = 0.0f;
#pragma unroll
    for (int f = 0; f < FN; f++) s = fmaf(prod[f], sLam[f], s);
    out[m] = s;
}

// ---------------- launch ----------------
extern "C" void kernel_launch(void* const* d_in, const int* in_sizes, int n_in,
                              void* d_out, int out_size) {
    const float* x   = (const float*)d_in[0];   // (M, 3)
    const float* fr  = (const float*)d_in[1];   // (3, 256, 16)
    const float* fi  = (const float*)d_in[2];   // (3, 256, 16)
    const float* lam = (const float*)d_in[3];   // (16,)
    float* out = (float*)d_out;                 // (M,)

    cond_kernel<<<NDIMS, 128>>>(fr, fi);

    const int smem_bytes = SMEM_FLOATS * (int)sizeof(float);
    cudaFuncSetAttribute(main_kernel,
                         cudaFuncAttributeMaxDynamicSharedMemorySize, smem_bytes);
    main_kernel<<<MTOT / 256, 256, smem_bytes>>>(x, fr, fi, lam, out);
}

// round 2
// speedup vs baseline: 1.5633x; 1.5633x over previous
#include <cuda_runtime.h>
#include <math.h>

#define NDIMS 3
#define HN    256          // H
#define FN    16           // F
#define MTOT  65536
#define TCOND 100
#define NJC   8            // j-chunks in cond kernel
#define JCW   (HN / NJC)   // 32 j per chunk

// conditionals c[n][f] = 1/trapz(relu(series(t)))
__device__ float g_c[NDIMS][FN];

// ---------------- packed f32x2 helpers ----------------
__device__ __forceinline__ unsigned long long pk2(float lo, float hi) {
    unsigned long long r;
    asm("mov.b64 %0, {%1, %2};" : "=l"(r) : "f"(lo), "f"(hi));
    return r;
}
__device__ __forceinline__ void upk2(unsigned long long v, float& lo, float& hi) {
    asm("mov.b64 {%0, %1}, %2;" : "=f"(lo), "=f"(hi) : "l"(v));
}
__device__ __forceinline__ unsigned long long fma2(unsigned long long a,
                                                   unsigned long long b,
                                                   unsigned long long c) {
    unsigned long long d;
    asm("fma.rn.f32x2 %0, %1, %2, %3;" : "=l"(d) : "l"(a), "l"(b), "l"(c));
    return d;
}
__device__ __forceinline__ unsigned long long mul2(unsigned long long a,
                                                   unsigned long long b) {
    unsigned long long d;
    asm("mul.rn.f32x2 %0, %1, %2;" : "=l"(d) : "l"(a), "l"(b));
    return d;
}

// ---------------- kernel 1: conditionals ----------------
// grid = NDIMS, block = 1024. Threads (t < 100) x (jc < 8) each handle a
// 32-wide j-chunk; deterministic two-stage smem reduction (no atomics).
// dynamic smem: sA[256][16], sB[256][16], part[8][100][16]
#define COND_SMEM_FLOATS (2 * HN * FN + NJC * TCOND * FN)

__global__ void __launch_bounds__(1024, 1)
cond_kernel(const float* __restrict__ fr, const float* __restrict__ fi) {
    extern __shared__ float csm[];
    float* sA   = csm;                      // [256][16]
    float* sB   = csm + HN * FN;            // [256][16]
    float* part = csm + 2 * HN * FN;        // [8][100][16]

    const int n = blockIdx.x;
    const int tid = threadIdx.x;

    for (int idx = tid; idx < HN * FN; idx += blockDim.x) {
        int f = idx & (FN - 1);
        int jm1 = idx >> 4;               // j-1, j = 1..256
        int src = (n * HN + (HN - 1 - jm1)) * FN + f;
        sA[idx] =  2.0f * fr[src];
        sB[idx] = -2.0f * fi[src];
    }
    __syncthreads();

    const int t_idx = tid & 127;
    const int jc    = tid >> 7;
    const float dt = 0.01f;

    if (t_idx < TCOND) {
        float t = 0.01f + dt * (float)t_idx;
        int jstart = jc * JCW + 1;
        float c, s, c1, s1;
        sincospif(2.0f * (float)jstart * t, &s, &c);   // angle 2*pi*jstart*t
        sincospif(2.0f * t, &s1, &c1);                 // step rotation
        float acc[FN];
#pragma unroll
        for (int f = 0; f < FN; f++) acc[f] = 0.0f;
        for (int jj = 0; jj < JCW; jj++) {
            int j0 = jc * JCW + jj;
#pragma unroll
            for (int f = 0; f < FN; f++)
                acc[f] += c * sA[j0 * FN + f] + s * sB[j0 * FN + f];
            float cn = fmaf(c, c1, -s * s1);
            float sn = fmaf(c, s1,  s * c1);
            c = cn; s = sn;
        }
#pragma unroll
        for (int f = 0; f < FN; f++)
            part[(jc * TCOND + t_idx) * FN + f] = acc[f];
    }
    __syncthreads();

    // stage 2: per-t sum over chunks, relu, trapz weight -> reuse part[0] rows
    if (jc == 0 && t_idx < TCOND) {
        float w = (t_idx == 0 || t_idx == TCOND - 1) ? 0.5f * dt : dt;
#pragma unroll
        for (int f = 0; f < FN; f++) {
            float v = 1.0f;
            for (int q = 0; q < NJC; q++)
                v += part[(q * TCOND + t_idx) * FN + f];
            part[t_idx * FN + f] = w * fmaxf(v, 0.0f);
        }
    }
    __syncthreads();

    // stage 3: sum over t (16 threads, one per f), deterministic order
    if (tid < FN) {
        float s = 0.0f;
        for (int t = 0; t < TCOND; t++)
            s += part[t * FN + tid];
        g_c[n][tid] = 1.0f / s;
    }
}

// ---------------- kernel 2: main ----------------
// grid = 128, block = 256, 2 samples per thread.
// dynamic smem: sA[3][256][16], sB[3][256][16] (prescaled by 2*c), sC[3][16], sLam[16]
#define SMEM_FLOATS (NDIMS * HN * FN * 2 + NDIMS * FN + FN)

__global__ void __launch_bounds__(256, 1)
main_kernel(const float* __restrict__ x,
            const float* __restrict__ fr,
            const float* __restrict__ fi,
            const float* __restrict__ lam,
            float* __restrict__ out) {
    extern __shared__ float smem[];
    float* sA   = smem;                          // 12288
    float* sB   = smem + NDIMS * HN * FN;        // 12288
    float* sC   = smem + 2 * NDIMS * HN * FN;    // 48
    float* sLam = sC + NDIMS * FN;               // 16

    const int tid = threadIdx.x;

    // fill factor tables (reversed in j, prescaled by 2*c[n][f])
    for (int idx = tid; idx < NDIMS * HN * FN; idx += blockDim.x) {
        int f   = idx & (FN - 1);
        int jm1 = (idx >> 4) & (HN - 1);
        int n   = idx >> 12;
        float c = g_c[n][f];
        int src = (n * HN + (HN - 1 - jm1)) * FN + f;
        sA[idx] =  2.0f * c * fr[src];
        sB[idx] = -2.0f * c * fi[src];
    }
    if (tid < NDIMS * FN) sC[tid] = ((const float*)g_c)[tid];
    if (tid < FN)         sLam[tid] = lam[tid];
    __syncthreads();

    const int m0 = blockIdx.x * 512 + tid;
    const int m1 = m0 + 256;
    float xs[2][NDIMS];
#pragma unroll
    for (int d = 0; d < NDIMS; d++) {
        xs[0][d] = x[m0 * 3 + d];
        xs[1][d] = x[m1 * 3 + d];
    }

    unsigned long long prod[2][8];

#pragma unroll
    for (int n = 0; n < NDIMS; n++) {
        // per-sample rotation constants (broadcast-packed)
        unsigned long long C1[2], S1[2], nS1[2], cc[2], ss[2];
#pragma unroll
        for (int sI = 0; sI < 2; sI++) {
            float c1, s1;
            sincospif(2.0f * xs[sI][n], &s1, &c1);
            C1[sI]  = pk2(c1, c1);
            S1[sI]  = pk2(s1, s1);
            nS1[sI] = pk2(-s1, -s1);
            cc[sI]  = C1[sI];    // j=1 state
            ss[sI]  = S1[sI];
        }

        const ulonglong2* An = (const ulonglong2*)(sA + n * HN * FN);
        const ulonglong2* Bn = (const ulonglong2*)(sB + n * HN * FN);
        const unsigned long long* c0 = (const unsigned long long*)(sC + n * FN);

        unsigned long long acc[2][8];
#pragma unroll
        for (int p = 0; p < 8; p++) {
            unsigned long long ci = c0[p];
            acc[0][p] = ci;                  // center term: c[n][f] * 1
            acc[1][p] = ci;
        }

#pragma unroll 2
        for (int j = 0; j < HN; j++) {
            ulonglong2 a0 = An[4 * j + 0];
            ulonglong2 a1 = An[4 * j + 1];
            ulonglong2 a2 = An[4 * j + 2];
            ulonglong2 a3 = An[4 * j + 3];
            ulonglong2 b0 = Bn[4 * j + 0];
            ulonglong2 b1 = Bn[4 * j + 1];
            ulonglong2 b2 = Bn[4 * j + 2];
            ulonglong2 b3 = Bn[4 * j + 3];

#pragma unroll
            for (int sI = 0; sI < 2; sI++) {
                acc[sI][0] = fma2(cc[sI], a0.x, acc[sI][0]);
                acc[sI][1] = fma2(cc[sI], a0.y, acc[sI][1]);
                acc[sI][2] = fma2(cc[sI], a1.x, acc[sI][2]);
                acc[sI][3] = fma2(cc[sI], a1.y, acc[sI][3]);
                acc[sI][4] = fma2(cc[sI], a2.x, acc[sI][4]);
                acc[sI][5] = fma2(cc[sI], a2.y, acc[sI][5]);
                acc[sI][6] = fma2(cc[sI], a3.x, acc[sI][6]);
                acc[sI][7] = fma2(cc[sI], a3.y, acc[sI][7]);
                acc[sI][0] = fma2(ss[sI], b0.x, acc[sI][0]);
                acc[sI][1] = fma2(ss[sI], b0.y, acc[sI][1]);
                acc[sI][2] = fma2(ss[sI], b1.x, acc[sI][2]);
                acc[sI][3] = fma2(ss[sI], b1.y, acc[sI][3]);
                acc[sI][4] = fma2(ss[sI], b2.x, acc[sI][4]);
                acc[sI][5] = fma2(ss[sI], b2.y, acc[sI][5]);
                acc[sI][6] = fma2(ss[sI], b3.x, acc[sI][6]);
                acc[sI][7] = fma2(ss[sI], b3.y, acc[sI][7]);
                // rotate in packed broadcast form (no unpack/pack):
                // cc' = cc*c1 - ss*s1 ; ss' = cc*s1 + ss*c1
                unsigned long long t0 = mul2(cc[sI], C1[sI]);
                unsigned long long t1 = mul2(cc[sI], S1[sI]);
                cc[sI] = fma2(ss[sI], nS1[sI], t0);
                ss[sI] = fma2(ss[sI], C1[sI],  t1);
            }
        }

        // relu & multiply into product
#pragma unroll
        for (int sI = 0; sI < 2; sI++) {
#pragma unroll
            for (int p = 0; p < 8; p++) {
                float lo, hi;
                upk2(acc[sI][p], lo, hi);
                unsigned long long r = pk2(fmaxf(lo, 0.0f), fmaxf(hi, 0.0f));
                prod[sI][p] = (n == 0) ? r : mul2(prod[sI][p], r);
            }
        }
    }

    // dot with lam
#pragma unroll
    for (int sI = 0; sI < 2; sI++) {
        float s = 0.0f;
#pragma unroll
        for (int p = 0; p < 8; p++) {
            float lo, hi;
            upk2(prod[sI][p], lo, hi);
            s = fmaf(lo, sLam[2 * p + 0], s);
            s = fmaf(hi, sLam[2 * p + 1], s);
        }
        out[(sI == 0) ? m0 : m1] = s;
    }
}

// ---------------- launch ----------------
extern "C" void kernel_launch(void* const* d_in, const int* in_sizes, int n_in,
                              void* d_out, int out_size) {
    const float* x   = (const float*)d_in[0];   // (M, 3)
    const float* fr  = (const float*)d_in[1];   // (3, 256, 16)
    const float* fi  = (const float*)d_in[2];   // (3, 256, 16)
    const float* lam = (const float*)d_in[3];   // (16,)
    float* out = (float*)d_out;                 // (M,)

    const int cond_smem = COND_SMEM_FLOATS * (int)sizeof(float);
    cudaFuncSetAttribute(cond_kernel,
                         cudaFuncAttributeMaxDynamicSharedMemorySize, cond_smem);
    cond_kernel<<<NDIMS, 1024, cond_smem>>>(fr, fi);

    const int smem_bytes = SMEM_FLOATS * (int)sizeof(float);
    cudaFuncSetAttribute(main_kernel,
                         cudaFuncAttributeMaxDynamicSharedMemorySize, smem_bytes);
    main_kernel<<<MTOT / 512, 256, smem_bytes>>>(x, fr, fi, lam, out);
}

// round 3
// speedup vs baseline: 3.5074x; 2.2436x over previous
#include <cuda_runtime.h>
#include <math.h>

#define NDIMS 3
#define HN    256          // H
#define FN    16           // F
#define MTOT  65536
#define TCOND 100
#define NJC   8            // j-chunks
#define JCW   (HN / NJC)   // 32

// ---- NUFFT parameters ----
#define NGRID 1024         // fine grid (oversampling ~2 for K=513)
#define WK    8            // window width (grid cells)
#define NPAD  (NGRID + 8)  // padded rows: row r holds l = r-3, r in [0,1031]
#define BETA  18.4f        // ES-kernel beta = 2.30*w

__device__ float g_c[NDIMS][FN];          // conditionals
__device__ float g_q[HN + 1];             // q_k = 1/(N*psihat(k))
__device__ __align__(16) float g_tab[NDIMS][NPAD][FN];   // deconvolved grid values (198KB)

// ---------------- packed f32x2 helpers ----------------
__device__ __forceinline__ unsigned long long pk2(float lo, float hi) {
    unsigned long long r;
    asm("mov.b64 %0, {%1, %2};" : "=l"(r) : "f"(lo), "f"(hi));
    return r;
}
__device__ __forceinline__ void upk2(unsigned long long v, float& lo, float& hi) {
    asm("mov.b64 {%0, %1}, %2;" : "=f"(lo), "=f"(hi) : "l"(v));
}
__device__ __forceinline__ unsigned long long fma2(unsigned long long a,
                                                   unsigned long long b,
                                                   unsigned long long c) {
    unsigned long long d;
    asm("fma.rn.f32x2 %0, %1, %2, %3;" : "=l"(d) : "l"(a), "l"(b), "l"(c));
    return d;
}
__device__ __forceinline__ unsigned long long mul2(unsigned long long a,
                                                   unsigned long long b) {
    unsigned long long d;
    asm("mul.rn.f32x2 %0, %1, %2;" : "=l"(d) : "l"(a), "l"(b));
    return d;
}

// ---------------- kernel A: window transform ----------------
// q_k = 1/(N * psihat(k)),  psihat(k) = (w/2N) * I_k,
// I_k = int_{-1}^{1} exp(beta*(sqrt(1-z^2)-1)) cos(pi*k*w*z/N) dz  (Simpson, 512)
// => q_k = 2/(w * I_k).  grid = 257 blocks (one per k), block = 128.
__global__ void psihat_kernel() {
    const int k = blockIdx.x;          // 0..256
    const int tid = threadIdx.x;       // 128
    const int NS = 512;
    const float h = 2.0f / NS;
    const float freq = (float)k * (float)WK / (float)NGRID;   // cospi(freq*z)
    float local = 0.0f;
    for (int i = tid; i <= NS; i += 128) {
        float z = -1.0f + h * (float)i;
        float phi = __expf(BETA * (sqrtf(fmaxf(1.0f - z * z, 0.0f)) - 1.0f));
        float w = (i == 0 || i == NS) ? 1.0f : ((i & 1) ? 4.0f : 2.0f);
        local += w * phi * cospif(freq * z);
    }
    __shared__ float red[4];
#pragma unroll
    for (int off = 16; off; off >>= 1)
        local += __shfl_down_sync(0xffffffffu, local, off);
    if ((tid & 31) == 0) red[tid >> 5] = local;
    __syncthreads();
    if (tid == 0) {
        float I = (red[0] + red[1] + red[2] + red[3]) * h * (1.0f / 3.0f);
        g_q[k] = 2.0f / ((float)WK * I);
    }
}

// ---------------- kernel B: conditionals ----------------
// (unchanged from round 2; deterministic two-stage reduction)
#define COND_SMEM_FLOATS (2 * HN * FN + NJC * TCOND * FN)
__global__ void __launch_bounds__(1024, 1)
cond_kernel(const float* __restrict__ fr, const float* __restrict__ fi) {
    extern __shared__ float csm[];
    float* sA   = csm;
    float* sB   = csm + HN * FN;
    float* part = csm + 2 * HN * FN;

    const int n = blockIdx.x;
    const int tid = threadIdx.x;

    for (int idx = tid; idx < HN * FN; idx += blockDim.x) {
        int f = idx & (FN - 1);
        int jm1 = idx >> 4;
        int src = (n * HN + (HN - 1 - jm1)) * FN + f;
        sA[idx] =  2.0f * fr[src];
        sB[idx] = -2.0f * fi[src];
    }
    __syncthreads();

    const int t_idx = tid & 127;
    const int jc    = tid >> 7;
    const float dt = 0.01f;

    if (t_idx < TCOND) {
        float t = 0.01f + dt * (float)t_idx;
        int jstart = jc * JCW + 1;
        float c, s, c1, s1;
        sincospif(2.0f * (float)jstart * t, &s, &c);
        sincospif(2.0f * t, &s1, &c1);
        float acc[FN];
#pragma unroll
        for (int f = 0; f < FN; f++) acc[f] = 0.0f;
        for (int jj = 0; jj < JCW; jj++) {
            int j0 = jc * JCW + jj;
#pragma unroll
            for (int f = 0; f < FN; f++)
                acc[f] += c * sA[j0 * FN + f] + s * sB[j0 * FN + f];
            float cn = fmaf(c, c1, -s * s1);
            float sn = fmaf(c, s1,  s * c1);
            c = cn; s = sn;
        }
#pragma unroll
        for (int f = 0; f < FN; f++)
            part[(jc * TCOND + t_idx) * FN + f] = acc[f];
    }
    __syncthreads();

    if (jc == 0 && t_idx < TCOND) {
        float w = (t_idx == 0 || t_idx == TCOND - 1) ? 0.5f * dt : dt;
#pragma unroll
        for (int f = 0; f < FN; f++) {
            float v = 1.0f;
            for (int q = 0; q < NJC; q++)
                v += part[(q * TCOND + t_idx) * FN + f];
            part[t_idx * FN + f] = w * fmaxf(v, 0.0f);
        }
    }
    __syncthreads();

    if (tid < FN) {
        float s = 0.0f;
        for (int t = 0; t < TCOND; t++)
            s += part[t * FN + tid];
        g_c[n][tid] = 1.0f / s;
    }
}

// ---------------- kernel C: build fine grid table ----------------
// g_tab[n][r][f] = c[n][f]*q0 + sum_j q_j*c*(2 fr_j cos(2pi j x_r) - 2 fi_j sin(...)),
// x_r = (r-3)/NGRID.  grid = (33, 3), block = 256 = 32 rows x 8 j-chunks.
#define GK_SMEM_FLOATS (2 * HN * FN + 32 * NJC * FN + FN)
__global__ void __launch_bounds__(256, 4)
grid_kernel(const float* __restrict__ fr, const float* __restrict__ fi) {
    extern __shared__ float sm[];
    float* sA   = sm;                       // [256][16]
    float* sB   = sm + HN * FN;             // [256][16]
    float* part = sm + 2 * HN * FN;         // [32][8][16]
    float* sCtr = part + 32 * NJC * FN;     // [16]

    const int n = blockIdx.y;
    const int tid = threadIdx.x;

    for (int idx = tid; idx < HN * FN; idx += 256) {
        int f = idx & (FN - 1);
        int jm1 = idx >> 4;                 // frequency j = jm1+1
        float cq = g_c[n][f] * g_q[jm1 + 1];
        int src = (n * HN + (HN - 1 - jm1)) * FN + f;
        sA[idx] =  2.0f * cq * fr[src];
        sB[idx] = -2.0f * cq * fi[src];
    }
    if (tid < FN) sCtr[tid] = g_c[n][tid] * g_q[0];
    __syncthreads();

    const int rl = tid & 31;
    const int jc = tid >> 5;
    const int r  = blockIdx.x * 32 + rl;
    {
        float xr = (float)(r - 3) * (1.0f / (float)NGRID);
        int jstart = jc * JCW + 1;
        float c, s, c1, s1;
        sincospif(2.0f * (float)jstart * xr, &s, &c);
        sincospif(2.0f * xr, &s1, &c1);
        float acc[FN];
#pragma unroll
        for (int f = 0; f < FN; f++) acc[f] = 0.0f;
        for (int jj = 0; jj < JCW; jj++) {
            int j0 = jc * JCW + jj;
#pragma unroll
            for (int f = 0; f < FN; f++)
                acc[f] += c * sA[j0 * FN + f] + s * sB[j0 * FN + f];
            float cn = fmaf(c, c1, -s * s1);
            float sn = fmaf(c, s1,  s * c1);
            c = cn; s = sn;
        }
#pragma unroll
        for (int f = 0; f < FN; f++)
            part[(rl * NJC + jc) * FN + f] = acc[f];
    }
    __syncthreads();

    for (int idx = tid; idx < 32 * FN; idx += 256) {
        int rl2 = idx >> 4;
        int f   = idx & (FN - 1);
        int rr  = blockIdx.x * 32 + rl2;
        if (rr < NPAD) {
            float v = sCtr[f];
#pragma unroll
            for (int q = 0; q < NJC; q++)
                v += part[(rl2 * NJC + q) * FN + f];
            g_tab[n][rr][f] = v;
        }
    }
}

// ---------------- kernel D: per-sample interpolation + relu-product + dot ----------------
__global__ void __launch_bounds__(256)
eval_kernel(const float* __restrict__ x,
            const float* __restrict__ lam,
            float* __restrict__ out) {
    __shared__ float sLam[FN];
    if (threadIdx.x < FN) sLam[threadIdx.x] = lam[threadIdx.x];
    __syncthreads();

    const int m = blockIdx.x * 256 + threadIdx.x;
    float xv0 = x[3 * m + 0];
    float xv1 = x[3 * m + 1];
    float xv2 = x[3 * m + 2];

    unsigned long long prod[8];

#pragma unroll
    for (int n = 0; n < NDIMS; n++) {
        const float xn = (n == 0) ? xv0 : (n == 1) ? xv1 : xv2;
        float xg = xn * (float)NGRID;
        float fl = floorf(xg);
        float d  = xg - fl;                 // [0,1)
        int r0   = (int)fl;                 // table row base (already padded by +3)

        unsigned long long acc[8];
#pragma unroll
        for (int p = 0; p < 8; p++) acc[p] = 0ull;

#pragma unroll
        for (int t = 0; t < WK; t++) {
            // z = (xg - (fl - 3 + t)) / (w/2) = (d + 3 - t) * 0.25
            float z = (d + (float)(3 - t)) * 0.25f;
            float wgt = __expf(BETA * (sqrtf(fmaxf(1.0f - z * z, 0.0f)) - 1.0f));
            unsigned long long wb = pk2(wgt, wgt);
            const ulonglong2* p4 = (const ulonglong2*)&g_tab[n][r0 + t][0];
            ulonglong2 v0 = p4[0];
            ulonglong2 v1 = p4[1];
            ulonglong2 v2 = p4[2];
            ulonglong2 v3 = p4[3];
            acc[0] = fma2(wb, v0.x, acc[0]);
            acc[1] = fma2(wb, v0.y, acc[1]);
            acc[2] = fma2(wb, v1.x, acc[2]);
            acc[3] = fma2(wb, v1.y, acc[3]);
            acc[4] = fma2(wb, v2.x, acc[4]);
            acc[5] = fma2(wb, v2.y, acc[5]);
            acc[6] = fma2(wb, v3.x, acc[6]);
            acc[7] = fma2(wb, v3.y, acc[7]);
        }

#pragma unroll
        for (int p = 0; p < 8; p++) {
            float lo, hi;
            upk2(acc[p], lo, hi);
            unsigned long long r = pk2(fmaxf(lo, 0.0f), fmaxf(hi, 0.0f));
            prod[p] = (n == 0) ? r : mul2(prod[p], r);
        }
    }

    float s = 0.0f;
#pragma unroll
    for (int p = 0; p < 8; p++) {
        float lo, hi;
        upk2(prod[p], lo, hi);
        s = fmaf(lo, sLam[2 * p + 0], s);
        s = fmaf(hi, sLam[2 * p + 1], s);
    }
    out[m] = s;
}

// ---------------- launch ----------------
extern "C" void kernel_launch(void* const* d_in, const int* in_sizes, int n_in,
                              void* d_out, int out_size) {
    const float* x   = (const float*)d_in[0];   // (M, 3)
    const float* fr  = (const float*)d_in[1];   // (3, 256, 16)
    const float* fi  = (const float*)d_in[2];   // (3, 256, 16)
    const float* lam = (const float*)d_in[3];   // (16,)
    float* out = (float*)d_out;                 // (M,)

    psihat_kernel<<<HN + 1, 128>>>();

    const int cond_smem = COND_SMEM_FLOATS * (int)sizeof(float);
    cudaFuncSetAttribute(cond_kernel,
                         cudaFuncAttributeMaxDynamicSharedMemorySize, cond_smem);
    cond_kernel<<<NDIMS, 1024, cond_smem>>>(fr, fi);

    const int gk_smem = GK_SMEM_FLOATS * (int)sizeof(float);
    cudaFuncSetAttribute(grid_kernel,
                         cudaFuncAttributeMaxDynamicSharedMemorySize, gk_smem);
    grid_kernel<<<dim3((NPAD + 31) / 32, NDIMS), 256, gk_smem>>>(fr, fi);

    eval_kernel<<<MTOT / 256, 256>>>(x, lam, out);
}

// round 5
// speedup vs baseline: 5.6804x; 1.6196x over previous
#include <cuda_runtime.h>
#include <math.h>

#define NDIMS 3
#define HN    256          // H
#define FN    16           // F
#define MTOT  65536
#define TCOND 100
#define NJC   8            // j-chunks
#define JCW   (HN / NJC)   // 32

// ---- NUFFT parameters ----
#define NGRID 768          // fine grid (sigma = 768/513 = 1.497)
#define WK    6            // window width (grid cells)
#define NPAD  (NGRID + 6)  // 774 rows; row r holds grid point l = r-2
#define RSTR  20           // row stride in floats (80B -> bank spread)
#define BETA  12.566371f   // pi*w*(1 - 1/(2*sigma))

__device__ float g_q[HN + 1];                              // 1/(N*psihat(k)) style deconv
__device__ __align__(16) float g_tab[NDIMS][NPAD][RSTR];   // c-free deconvolved grid
__device__ float g_lam2[FN];                               // lam * c0*c1*c2

// ---------------- packed f32x2 helpers ----------------
__device__ __forceinline__ unsigned long long pk2(float lo, float hi) {
    unsigned long long r;
    asm("mov.b64 %0, {%1, %2};" : "=l"(r) : "f"(lo), "f"(hi));
    return r;
}
__device__ __forceinline__ void upk2(unsigned long long v, float& lo, float& hi) {
    asm("mov.b64 {%0, %1}, %2;" : "=f"(lo), "=f"(hi) : "l"(v));
}
__device__ __forceinline__ unsigned long long fma2(unsigned long long a,
                                                   unsigned long long b,
                                                   unsigned long long c) {
    unsigned long long d;
    asm("fma.rn.f32x2 %0, %1, %2, %3;" : "=l"(d) : "l"(a), "l"(b), "l"(c));
    return d;
}
__device__ __forceinline__ unsigned long long mul2(unsigned long long a,
                                                   unsigned long long b) {
    unsigned long long d;
    asm("mul.rn.f32x2 %0, %1, %2;" : "=l"(d) : "l"(a), "l"(b));
    return d;
}

// ES window weight
__device__ __forceinline__ float es_w(float z) {
    float s2 = fmaxf(1.0f - z * z, 0.0f);
    return __expf(BETA * (sqrtf(s2) - 1.0f));
}

// ---------------- kernel A: window transform ----------------
// q_k = 2/(w * I_k), I_k = int_{-1}^{1} e^{beta(sqrt(1-z^2)-1)} cos(pi*k*w*z/N) dz
__global__ void psihat_kernel() {
    const int k = blockIdx.x;          // 0..256
    const int tid = threadIdx.x;       // 128
    const int NS = 512;
    const float h = 2.0f / NS;
    const float freq = (float)k * (float)WK / (float)NGRID;
    float local = 0.0f;
    for (int i = tid; i <= NS; i += 128) {
        float z = -1.0f + h * (float)i;
        float phi = __expf(BETA * (sqrtf(fmaxf(1.0f - z * z, 0.0f)) - 1.0f));
        float w = (i == 0 || i == NS) ? 1.0f : ((i & 1) ? 4.0f : 2.0f);
        local += w * phi * cospif(freq * z);
    }
    __shared__ float red[4];
#pragma unroll
    for (int off = 16; off; off >>= 1)
        local += __shfl_down_sync(0xffffffffu, local, off);
    if ((tid & 31) == 0) red[tid >> 5] = local;
    __syncthreads();
    if (tid == 0) {
        float I = (red[0] + red[1] + red[2] + red[3]) * h * (1.0f / 3.0f);
        g_q[k] = 2.0f / ((float)WK * I);
    }
}

// ---------------- kernel B: build fine-grid table (c-free) ----------------
// tab[n][r][f] = q0 + sum_j q_j*(2 fr~_j cos(2pi j x_r) - 2 fi~_j sin(2pi j x_r)),
// x_r = (r-2)/NGRID.  grid = (25, 3), block = 256 = 32 rows x 8 j-chunks.
#define GK_SMEM_FLOATS (2 * HN * FN + 32 * NJC * FN)
__global__ void __launch_bounds__(256, 4)
grid_kernel(const float* __restrict__ fr, const float* __restrict__ fi) {
    extern __shared__ float sm[];
    float* sA   = sm;                       // [256][16] : 2*q_j*fr (reversed j)
    float* sB   = sm + HN * FN;             // [256][16] : -2*q_j*fi (reversed j)
    float* part = sm + 2 * HN * FN;         // [32][8][16]

    const int n = blockIdx.y;
    const int tid = threadIdx.x;

    for (int idx = tid; idx < HN * FN; idx += 256) {
        int f = idx & (FN - 1);
        int jm1 = idx >> 4;                 // frequency j = jm1+1
        float q = g_q[jm1 + 1];
        int src = (n * HN + (HN - 1 - jm1)) * FN + f;
        sA[idx] =  2.0f * q * fr[src];
        sB[idx] = -2.0f * q * fi[src];
    }
    __syncthreads();

    const int rl = tid & 31;
    const int jc = tid >> 5;
    const int r  = blockIdx.x * 32 + rl;
    {
        float xr = (float)(r - 2) * (1.0f / (float)NGRID);
        int jstart = jc * JCW + 1;
        float c0, s0, c1, s1;
        sincospif(2.0f * (float)jstart * xr, &s0, &c0);
        sincospif(2.0f * xr, &s1, &c1);
        unsigned long long cc = pk2(c0, c0), ss = pk2(s0, s0);
        unsigned long long C1 = pk2(c1, c1), S1 = pk2(s1, s1), nS1 = pk2(-s1, -s1);

        const ulonglong2* An = (const ulonglong2*)sA;   // 4 ulonglong2 per j-row
        const ulonglong2* Bn = (const ulonglong2*)sB;

        unsigned long long acc[8];                      // 8 packed pairs = 16 f
#pragma unroll
        for (int p = 0; p < 8; p++) acc[p] = 0ull;

        for (int jj = 0; jj < JCW; jj++) {
            int j0 = jc * JCW + jj;
            ulonglong2 a0 = An[4 * j0 + 0];
            ulonglong2 a1 = An[4 * j0 + 1];
            ulonglong2 a2 = An[4 * j0 + 2];
            ulonglong2 a3 = An[4 * j0 + 3];
            ulonglong2 b0 = Bn[4 * j0 + 0];
            ulonglong2 b1 = Bn[4 * j0 + 1];
            ulonglong2 b2 = Bn[4 * j0 + 2];
            ulonglong2 b3 = Bn[4 * j0 + 3];

            acc[0] = fma2(cc, a0.x, acc[0]);
            acc[1] = fma2(cc, a0.y, acc[1]);
            acc[2] = fma2(cc, a1.x, acc[2]);
            acc[3] = fma2(cc, a1.y, acc[3]);
            acc[4] = fma2(cc, a2.x, acc[4]);
            acc[5] = fma2(cc, a2.y, acc[5]);
            acc[6] = fma2(cc, a3.x, acc[6]);
            acc[7] = fma2(cc, a3.y, acc[7]);
            acc[0] = fma2(ss, b0.x, acc[0]);
            acc[1] = fma2(ss, b0.y, acc[1]);
            acc[2] = fma2(ss, b1.x, acc[2]);
            acc[3] = fma2(ss, b1.y, acc[3]);
            acc[4] = fma2(ss, b2.x, acc[4]);
            acc[5] = fma2(ss, b2.y, acc[5]);
            acc[6] = fma2(ss, b3.x, acc[6]);
            acc[7] = fma2(ss, b3.y, acc[7]);

            unsigned long long t0 = mul2(cc, C1);
            unsigned long long t1 = mul2(cc, S1);
            cc = fma2(ss, nS1, t0);
            ss = fma2(ss, C1,  t1);
        }

        float* pp = &part[(rl * NJC + jc) * FN];
#pragma unroll
        for (int p = 0; p < 8; p++) {
            float lo, hi;
            upk2(acc[p], lo, hi);
            pp[2 * p + 0] = lo;
            pp[2 * p + 1] = hi;
        }
    }
    __syncthreads();

    const float q0 = g_q[0];
    for (int idx = tid; idx < 32 * FN; idx += 256) {
        int rl2 = idx >> 4;
        int f   = idx & (FN - 1);
        int rr  = blockIdx.x * 32 + rl2;
        if (rr < NPAD) {
            float v = q0;
#pragma unroll
            for (int q = 0; q < NJC; q++)
                v += part[(rl2 * NJC + q) * FN + f];
            g_tab[n][rr][f] = v;
        }
    }
}

// ---------------- kernel C: conditionals via table -> lam' ----------------
// one block of 512: (n,i) interp at t_i, trapz, c = 1/integ, lam' = lam*prod(c)
__global__ void __launch_bounds__(512, 1)
lamprep_kernel(const float* __restrict__ lam) {
    __shared__ float part[NDIMS * TCOND * FN];   // 19.2KB
    __shared__ float sc[NDIMS * FN];

    const int tid = threadIdx.x;
    const int n = tid >> 7;          // 0..3
    const int i = tid & 127;

    if (n < NDIMS && i < TCOND) {
        float t = 0.01f + 0.01f * (float)i;
        float xg = t * (float)NGRID;
        float fl = floorf(xg);
        float d  = xg - fl;
        int r0   = (int)fl;
        const float* rowp = &g_tab[n][r0][0];
        float acc[FN];
#pragma unroll
        for (int f = 0; f < FN; f++) acc[f] = 0.0f;
#pragma unroll
        for (int tt = 0; tt < WK; tt++) {
            float z = (d + (float)(2 - tt)) * (1.0f / 3.0f);
            float wgt = es_w(z);
            const float4* p4 = (const float4*)(rowp + tt * RSTR);
#pragma unroll
            for (int cq = 0; cq < 4; cq++) {
                float4 v = p4[cq];
                acc[4 * cq + 0] = fmaf(wgt, v.x, acc[4 * cq + 0]);
                acc[4 * cq + 1] = fmaf(wgt, v.y, acc[4 * cq + 1]);
                acc[4 * cq + 2] = fmaf(wgt, v.z, acc[4 * cq + 2]);
                acc[4 * cq + 3] = fmaf(wgt, v.w, acc[4 * cq + 3]);
            }
        }
        float wt = (i == 0 || i == TCOND - 1) ? 0.005f : 0.01f;
#pragma unroll
        for (int f = 0; f < FN; f++)
            part[(n * TCOND + i) * FN + f] = wt * fmaxf(acc[f], 0.0f);
    }
    __syncthreads();

    if (tid < NDIMS * FN) {
        int nn = tid >> 4;
        int f  = tid & 15;
        float s = 0.0f;
        for (int q = 0; q < TCOND; q++)
            s += part[(nn * TCOND + q) * FN + f];
        sc[tid] = 1.0f / s;
    }
    __syncthreads();
    if (tid < FN)
        g_lam2[tid] = lam[tid] * sc[tid] * sc[FN + tid] * sc[2 * FN + tid];
}

// ---------------- kernel D: eval (smem-resident table) ----------------
#define TAB_FLOATS (NDIMS * NPAD * RSTR)     // 46440 floats = 181.4KB
#define EV_SMEM_BYTES ((TAB_FLOATS + FN) * 4)

__global__ void __launch_bounds__(512, 1)
eval_kernel(const float* __restrict__ x, float* __restrict__ out) {
    extern __shared__ float sm[];
    float* tab   = sm;                 // 46440 floats
    float* sLam2 = sm + TAB_FLOATS;

    const int tid = threadIdx.x;

    // broadcast table L2 -> smem (straight copy, stride preserved)
    {
        const float4* src = (const float4*)&g_tab[0][0][0];
        float4* dst = (float4*)tab;
        for (int idx = tid; idx < TAB_FLOATS / 4; idx += 512)
            dst[idx] = src[idx];
    }
    if (tid < FN) sLam2[tid] = g_lam2[tid];
    __syncthreads();

    const int m = blockIdx.x * 512 + tid;
    const float xv0 = x[3 * m + 0];
    const float xv1 = x[3 * m + 1];
    const float xv2 = x[3 * m + 2];

    unsigned long long prod[8];

#pragma unroll
    for (int n = 0; n < NDIMS; n++) {
        const float xn = (n == 0) ? xv0 : (n == 1) ? xv1 : xv2;
        float xg = xn * (float)NGRID;
        float fl = floorf(xg);
        float d  = xg - fl;
        int r0   = (int)fl;
        const float* rowp = tab + n * (NPAD * RSTR) + r0 * RSTR;

        unsigned long long acc[8];
#pragma unroll
        for (int p = 0; p < 8; p++) acc[p] = 0ull;

#pragma unroll
        for (int t = 0; t < WK; t++) {
            float z = (d + (float)(2 - t)) * (1.0f / 3.0f);
            float wgt = es_w(z);
            unsigned long long wb = pk2(wgt, wgt);
            const ulonglong2* p4 = (const ulonglong2*)(rowp + t * RSTR);
            ulonglong2 v0 = p4[0];
            ulonglong2 v1 = p4[1];
            ulonglong2 v2 = p4[2];
            ulonglong2 v3 = p4[3];
            acc[0] = fma2(wb, v0.x, acc[0]);
            acc[1] = fma2(wb, v0.y, acc[1]);
            acc[2] = fma2(wb, v1.x, acc[2]);
            acc[3] = fma2(wb, v1.y, acc[3]);
            acc[4] = fma2(wb, v2.x, acc[4]);
            acc[5] = fma2(wb, v2.y, acc[5]);
            acc[6] = fma2(wb, v3.x, acc[6]);
            acc[7] = fma2(wb, v3.y, acc[7]);
        }

#pragma unroll
        for (int p = 0; p < 8; p++) {
            float lo, hi;
            upk2(acc[p], lo, hi);
            unsigned long long r = pk2(fmaxf(lo, 0.0f), fmaxf(hi, 0.0f));
            prod[p] = (n == 0) ? r : mul2(prod[p], r);
        }
    }

    float s = 0.0f;
#pragma unroll
    for (int p = 0; p < 8; p++) {
        float lo, hi;
        upk2(prod[p], lo, hi);
        s = fmaf(lo, sLam2[2 * p + 0], s);
        s = fmaf(hi, sLam2[2 * p + 1], s);
    }
    out[m] = s;
}

// ---------------- launch ----------------
extern "C" void kernel_launch(void* const* d_in, const int* in_sizes, int n_in,
                              void* d_out, int out_size) {
    const float* x   = (const float*)d_in[0];   // (M, 3)
    const float* fr  = (const float*)d_in[1];   // (3, 256, 16)
    const float* fi  = (const float*)d_in[2];   // (3, 256, 16)
    const float* lam = (const float*)d_in[3];   // (16,)
    float* out = (float*)d_out;                 // (M,)

    psihat_kernel<<<HN + 1, 128>>>();

    const int gk_smem = GK_SMEM_FLOATS * (int)sizeof(float);
    cudaFuncSetAttribute(grid_kernel,
                         cudaFuncAttributeMaxDynamicSharedMemorySize, gk_smem);
    grid_kernel<<<dim3((NPAD + 31) / 32, NDIMS), 256, gk_smem>>>(fr, fi);

    lamprep_kernel<<<1, 512>>>(lam);

    cudaFuncSetAttribute(eval_kernel,
                         cudaFuncAttributeMaxDynamicSharedMemorySize, EV_SMEM_BYTES);
    eval_kernel<<<MTOT / 512, 512, EV_SMEM_BYTES>>>(x, out);
}

// round 7
// speedup vs baseline: 6.1051x; 1.0748x over previous
#include <cuda_runtime.h>
#include <math.h>

#define NDIMS 3
#define HN    256
#define FN    16
#define MTOT  65536
#define TCOND 100
#define NJC   8
#define JCW   (HN / NJC)

// ---- NUFFT parameters ----
#define NGRID 768          // sigma = 768/513 = 1.497
#define WK    6            // window width
#define NPAD  (NGRID + 6)  // 774 rows; row r <-> grid point l = r-2
#define RSTR  20           // row stride in floats (80B)
#define BETA  12.566371f   // pi*w*(1 - 1/(2*sigma))
#define NSQ   64           // Simpson intervals for psihat (65 pts)

__device__ __align__(16) float g_tab[NDIMS][NPAD][RSTR];

// ---------------- packed f32x2 helpers ----------------
__device__ __forceinline__ unsigned long long pk2(float lo, float hi) {
    unsigned long long r;
    asm("mov.b64 %0, {%1, %2};" : "=l"(r) : "f"(lo), "f"(hi));
    return r;
}
__device__ __forceinline__ void upk2(unsigned long long v, float& lo, float& hi) {
    asm("mov.b64 {%0, %1}, %2;" : "=f"(lo), "=f"(hi) : "l"(v));
}
__device__ __forceinline__ unsigned long long fma2(unsigned long long a,
                                                   unsigned long long b,
                                                   unsigned long long c) {
    unsigned long long d;
    asm("fma.rn.f32x2 %0, %1, %2, %3;" : "=l"(d) : "l"(a), "l"(b), "l"(c));
    return d;
}
__device__ __forceinline__ unsigned long long mul2(unsigned long long a,
                                                   unsigned long long b) {
    unsigned long long d;
    asm("mul.rn.f32x2 %0, %1, %2;" : "=l"(d) : "l"(a), "l"(b));
    return d;
}
__device__ __forceinline__ float es_w(float z) {
    float s2 = fmaxf(1.0f - z * z, 0.0f);
    return __expf(BETA * (sqrtf(s2) - 1.0f));
}

// ---------------- kernel 1: fused psihat + fine-grid table build ----------------
// grid = (25, 3), block = 256.
// smem layout (floats): sq[257] @0 | sphi[65] @257 | (pad) | sA @328 | sB | part
// 328*4 = 1312 bytes, 16B-aligned; sA/sB sizes are multiples of 16 floats.
#define PREP_SQ    0
#define PREP_PHI   257
#define PREP_A     328                       // 16B-aligned (328 % 4 == 0)
#define PREP_B     (PREP_A + HN * FN)        // 328 + 4096
#define PREP_PART  (PREP_B + HN * FN)
#define PREP_FLOATS (PREP_PART + 32 * NJC * FN)

__global__ void __launch_bounds__(256, 4)
prep_kernel(const float* __restrict__ fr, const float* __restrict__ fi) {
    extern __shared__ float sm[];
    float* sq   = sm + PREP_SQ;
    float* sphi = sm + PREP_PHI;
    float* sA   = sm + PREP_A;
    float* sB   = sm + PREP_B;
    float* part = sm + PREP_PART;

    const int n = blockIdx.y;
    const int tid = threadIdx.x;

    // stage 0: ES bump * simpson coeff * h/3 at 65 nodes
    if (tid <= NSQ) {
        float z = -1.0f + (float)tid * (2.0f / NSQ);
        float phi = __expf(BETA * (sqrtf(fmaxf(1.0f - z * z, 0.0f)) - 1.0f));
        float cI = (tid == 0 || tid == NSQ) ? 1.0f : ((tid & 1) ? 4.0f : 2.0f);
        sphi[tid] = cI * phi * ((2.0f / NSQ) / 3.0f);
    }
    __syncthreads();

    // stage 1: q_k = 2 / (w * I_k)
    {
        int k = tid + 1;
        float freq = (float)k * ((float)WK / (float)NGRID);
        float I = 0.0f;
#pragma unroll 4
        for (int i = 0; i <= NSQ; i++) {
            float z = -1.0f + (float)i * (2.0f / NSQ);
            I += sphi[i] * cospif(freq * z);
        }
        sq[k] = 2.0f / ((float)WK * I);
        if (tid == 0) {
            float I0 = 0.0f;
            for (int i = 0; i <= NSQ; i++) I0 += sphi[i];
            sq[0] = 2.0f / ((float)WK * I0);
        }
    }
    __syncthreads();

    // stage 2: deconvolved factor tables (reversed j, scaled by q_j)
    for (int idx = tid; idx < HN * FN; idx += 256) {
        int f = idx & (FN - 1);
        int jm1 = idx >> 4;                 // j = jm1+1
        float q = sq[jm1 + 1];
        int src = (n * HN + (HN - 1 - jm1)) * FN + f;
        sA[idx] =  2.0f * q * fr[src];
        sB[idx] = -2.0f * q * fi[src];
    }
    __syncthreads();

    // stage 3: series at 32 rows x 8 j-chunks
    const int rl = tid & 31;
    const int jc = tid >> 5;
    const int r  = blockIdx.x * 32 + rl;
    {
        float xr = (float)(r - 2) * (1.0f / (float)NGRID);
        int jstart = jc * JCW + 1;
        float c0, s0, c1, s1;
        sincospif(2.0f * (float)jstart * xr, &s0, &c0);
        sincospif(2.0f * xr, &s1, &c1);
        unsigned long long cc = pk2(c0, c0), ss = pk2(s0, s0);
        unsigned long long C1 = pk2(c1, c1), S1 = pk2(s1, s1), nS1 = pk2(-s1, -s1);

        const ulonglong2* An = (const ulonglong2*)sA;
        const ulonglong2* Bn = (const ulonglong2*)sB;

        unsigned long long acc[8];
#pragma unroll
        for (int p = 0; p < 8; p++) acc[p] = 0ull;

        for (int jj = 0; jj < JCW; jj++) {
            int j0 = jc * JCW + jj;
            ulonglong2 a0 = An[4 * j0 + 0];
            ulonglong2 a1 = An[4 * j0 + 1];
            ulonglong2 a2 = An[4 * j0 + 2];
            ulonglong2 a3 = An[4 * j0 + 3];
            ulonglong2 b0 = Bn[4 * j0 + 0];
            ulonglong2 b1 = Bn[4 * j0 + 1];
            ulonglong2 b2 = Bn[4 * j0 + 2];
            ulonglong2 b3 = Bn[4 * j0 + 3];

            acc[0] = fma2(cc, a0.x, acc[0]);
            acc[1] = fma2(cc, a0.y, acc[1]);
            acc[2] = fma2(cc, a1.x, acc[2]);
            acc[3] = fma2(cc, a1.y, acc[3]);
            acc[4] = fma2(cc, a2.x, acc[4]);
            acc[5] = fma2(cc, a2.y, acc[5]);
            acc[6] = fma2(cc, a3.x, acc[6]);
            acc[7] = fma2(cc, a3.y, acc[7]);
            acc[0] = fma2(ss, b0.x, acc[0]);
            acc[1] = fma2(ss, b0.y, acc[1]);
            acc[2] = fma2(ss, b1.x, acc[2]);
            acc[3] = fma2(ss, b1.y, acc[3]);
            acc[4] = fma2(ss, b2.x, acc[4]);
            acc[5] = fma2(ss, b2.y, acc[5]);
            acc[6] = fma2(ss, b3.x, acc[6]);
            acc[7] = fma2(ss, b3.y, acc[7]);

            unsigned long long t0 = mul2(cc, C1);
            unsigned long long t1 = mul2(cc, S1);
            cc = fma2(ss, nS1, t0);
            ss = fma2(ss, C1,  t1);
        }

        float* pp = &part[(rl * NJC + jc) * FN];
#pragma unroll
        for (int p = 0; p < 8; p++) {
            float lo, hi;
            upk2(acc[p], lo, hi);
            pp[2 * p + 0] = lo;
            pp[2 * p + 1] = hi;
        }
    }
    __syncthreads();

    const float q0 = sq[0];
    for (int idx = tid; idx < 32 * FN; idx += 256) {
        int rl2 = idx >> 4;
        int f   = idx & (FN - 1);
        int rr  = blockIdx.x * 32 + rl2;
        if (rr < NPAD) {
            float v = q0;
#pragma unroll
            for (int q = 0; q < NJC; q++)
                v += part[(rl2 * NJC + q) * FN + f];
            g_tab[n][rr][f] = v;
        }
    }
}

// ---------------- kernel 2: fused lamprep + eval ----------------
// grid = 128, block = 1024, 2 threads per sample (f split 8+8).
// smem: tab[46440] | lpart[300*16] | sc[48] | sLam2[16]
#define TAB_FLOATS (NDIMS * NPAD * RSTR)                 // 46440
#define EV_LPART   TAB_FLOATS
#define EV_SC      (EV_LPART + NDIMS * TCOND * FN)       // +4800
#define EV_LAM2    (EV_SC + NDIMS * FN)                  // +48
#define EV_FLOATS  (EV_LAM2 + FN)
#define EV_SMEM_BYTES (EV_FLOATS * 4)

__global__ void __launch_bounds__(1024, 1)
eval_kernel(const float* __restrict__ x,
            const float* __restrict__ lam,
            float* __restrict__ out) {
    extern __shared__ float sm[];
    float* tab   = sm;
    float* lpart = sm + EV_LPART;
    float* sc    = sm + EV_SC;
    float* sLam2 = sm + EV_LAM2;

    const int tid = threadIdx.x;

    // table broadcast L2 -> smem
    {
        const float4* src = (const float4*)&g_tab[0][0][0];
        float4* dst = (float4*)tab;
        for (int idx = tid; idx < TAB_FLOATS / 4; idx += 1024)
            dst[idx] = src[idx];
    }
    __syncthreads();

    // --- fused lamprep stage 1: 300 interpolations (t-grid), weighted relu ---
    if (tid < NDIMS * TCOND) {
        int n = tid / TCOND;
        int i = tid - n * TCOND;
        float t = 0.01f + 0.01f * (float)i;
        float xg = t * (float)NGRID;
        float fl = floorf(xg);
        float d  = xg - fl;
        int r0   = (int)fl;
        const float* rowp = tab + n * (NPAD * RSTR) + r0 * RSTR;
        float acc[FN];
#pragma unroll
        for (int f = 0; f < FN; f++) acc[f] = 0.0f;
#pragma unroll
        for (int tt = 0; tt < WK; tt++) {
            float z = (d + (float)(2 - tt)) * (1.0f / 3.0f);
            float wgt = es_w(z);
            const float4* p4 = (const float4*)(rowp + tt * RSTR);
#pragma unroll
            for (int cq = 0; cq < 4; cq++) {
                float4 v = p4[cq];
                acc[4 * cq + 0] = fmaf(wgt, v.x, acc[4 * cq + 0]);
                acc[4 * cq + 1] = fmaf(wgt, v.y, acc[4 * cq + 1]);
                acc[4 * cq + 2] = fmaf(wgt, v.z, acc[4 * cq + 2]);
                acc[4 * cq + 3] = fmaf(wgt, v.w, acc[4 * cq + 3]);
            }
        }
        float wt = (i == 0 || i == TCOND - 1) ? 0.005f : 0.01f;
#pragma unroll
        for (int f = 0; f < FN; f++)
            lpart[tid * FN + f] = wt * fmaxf(acc[f], 0.0f);
    }

    // --- main eval: sample m, half h (f channels h*8 .. h*8+7) ---
    const int h = tid & 1;
    const int m = blockIdx.x * 512 + (tid >> 1);
    const float xv0 = x[3 * m + 0];
    const float xv1 = x[3 * m + 1];
    const float xv2 = x[3 * m + 2];

    unsigned long long prod[4];

#pragma unroll
    for (int n = 0; n < NDIMS; n++) {
        const float xn = (n == 0) ? xv0 : (n == 1) ? xv1 : xv2;
        float xg = xn * (float)NGRID;
        float fl = floorf(xg);
        float d  = xg - fl;
        int r0   = (int)fl;
        const float* rowp = tab + n * (NPAD * RSTR) + r0 * RSTR + h * 8;

        unsigned long long acc[4];
#pragma unroll
        for (int p = 0; p < 4; p++) acc[p] = 0ull;

#pragma unroll
        for (int t = 0; t < WK; t++) {
            float z = (d + (float)(2 - t)) * (1.0f / 3.0f);
            float wgt = es_w(z);
            unsigned long long wb = pk2(wgt, wgt);
            const ulonglong2* p4 = (const ulonglong2*)(rowp + t * RSTR);
            ulonglong2 v0 = p4[0];
            ulonglong2 v1 = p4[1];
            acc[0] = fma2(wb, v0.x, acc[0]);
            acc[1] = fma2(wb, v0.y, acc[1]);
            acc[2] = fma2(wb, v1.x, acc[2]);
            acc[3] = fma2(wb, v1.y, acc[3]);
        }

#pragma unroll
        for (int p = 0; p < 4; p++) {
            float lo, hi;
            upk2(acc[p], lo, hi);
            unsigned long long r = pk2(fmaxf(lo, 0.0f), fmaxf(hi, 0.0f));
            prod[p] = (n == 0) ? r : mul2(prod[p], r);
        }
    }

    __syncthreads();   // lpart complete

    // --- lamprep stage 2: trapz sum over t, c = 1/integral ---
    if (tid < NDIMS * FN) {
        int nn = tid >> 4;
        int f  = tid & 15;
        float s = 0.0f;
        for (int q = 0; q < TCOND; q++)
            s += lpart[(nn * TCOND + q) * FN + f];
        sc[tid] = 1.0f / s;
    }
    __syncthreads();

    if (tid < FN)
        sLam2[tid] = lam[tid] * sc[tid] * sc[FN + tid] * sc[2 * FN + tid];
    __syncthreads();

    // --- dot with lam', combine halves, write ---
    float s = 0.0f;
#pragma unroll
    for (int p = 0; p < 4; p++) {
        float lo, hi;
        upk2(prod[p], lo, hi);
        s = fmaf(lo, sLam2[h * 8 + 2 * p + 0], s);
        s = fmaf(hi, sLam2[h * 8 + 2 * p + 1], s);
    }
    s += __shfl_xor_sync(0xffffffffu, s, 1);
    if (h == 0) out[m] = s;
}

// ---------------- launch ----------------
extern "C" void kernel_launch(void* const* d_in, const int* in_sizes, int n_in,
                              void* d_out, int out_size) {
    const float* x   = (const float*)d_in[0];
    const float* fr  = (const float*)d_in[1];
    const float* fi  = (const float*)d_in[2];
    const float* lam = (const float*)d_in[3];
    float* out = (float*)d_out;

    const int prep_smem = PREP_FLOATS * (int)sizeof(float);
    cudaFuncSetAttribute(prep_kernel,
                         cudaFuncAttributeMaxDynamicSharedMemorySize, prep_smem);
    prep_kernel<<<dim3((NPAD + 31) / 32, NDIMS), 256, prep_smem>>>(fr, fi);

    cudaFuncSetAttribute(eval_kernel,
                         cudaFuncAttributeMaxDynamicSharedMemorySize, EV_SMEM_BYTES);
    eval_kernel<<<MTOT / 512, 1024, EV_SMEM_BYTES>>>(x, lam, out);
}

// round 8
// speedup vs baseline: 6.6743x; 1.0932x over previous
#include <cuda_runtime.h>
#include <math.h>

#define NDIMS 3
#define HN    256
#define FN    16
#define MTOT  65536
#define TCOND 100
#define NJC   8
#define JCW   (HN / NJC)

// ---- NUFFT parameters ----
#define NGRID 768          // sigma = 768/513 = 1.497
#define WK    6            // window width
#define NPAD  (NGRID + 6)  // 774 rows; row r <-> grid point l = r-2
#define RSTR  20           // row stride in floats (80B)
#define BETA  12.566371f   // pi*w*(1 - 1/(2*sigma))
#define NSQ   64           // Simpson intervals for psihat

#define NBLK  148          // eval grid = one block per SM
#define SPB   443          // samples per block (148*443 = 65564 >= 65536)

__device__ __align__(16) float g_tab[NDIMS][NPAD][RSTR];

// ---------------- packed f32x2 helpers ----------------
__device__ __forceinline__ unsigned long long pk2(float lo, float hi) {
    unsigned long long r;
    asm("mov.b64 %0, {%1, %2};" : "=l"(r) : "f"(lo), "f"(hi));
    return r;
}
__device__ __forceinline__ void upk2(unsigned long long v, float& lo, float& hi) {
    asm("mov.b64 {%0, %1}, %2;" : "=f"(lo), "=f"(hi) : "l"(v));
}
__device__ __forceinline__ unsigned long long fma2(unsigned long long a,
                                                   unsigned long long b,
                                                   unsigned long long c) {
    unsigned long long d;
    asm("fma.rn.f32x2 %0, %1, %2, %3;" : "=l"(d) : "l"(a), "l"(b), "l"(c));
    return d;
}
__device__ __forceinline__ unsigned long long mul2(unsigned long long a,
                                                   unsigned long long b) {
    unsigned long long d;
    asm("mul.rn.f32x2 %0, %1, %2;" : "=l"(d) : "l"(a), "l"(b));
    return d;
}
__device__ __forceinline__ float es_w(float z) {
    float s2 = fmaxf(1.0f - z * z, 0.0f);
    return __expf(BETA * (sqrtf(s2) - 1.0f));
}

// ---------------- kernel 1: fused psihat + fine-grid table build ----------------
// grid = (25, 3), block = 256.  (identical to round 7, which passed)
#define PREP_SQ    0
#define PREP_PHI   257
#define PREP_A     328                       // 16B-aligned
#define PREP_B     (PREP_A + HN * FN)
#define PREP_PART  (PREP_B + HN * FN)
#define PREP_FLOATS (PREP_PART + 32 * NJC * FN)

__global__ void __launch_bounds__(256, 4)
prep_kernel(const float* __restrict__ fr, const float* __restrict__ fi) {
    extern __shared__ float sm[];
    float* sq   = sm + PREP_SQ;
    float* sphi = sm + PREP_PHI;
    float* sA   = sm + PREP_A;
    float* sB   = sm + PREP_B;
    float* part = sm + PREP_PART;

    const int n = blockIdx.y;
    const int tid = threadIdx.x;

    if (tid <= NSQ) {
        float z = -1.0f + (float)tid * (2.0f / NSQ);
        float phi = __expf(BETA * (sqrtf(fmaxf(1.0f - z * z, 0.0f)) - 1.0f));
        float cI = (tid == 0 || tid == NSQ) ? 1.0f : ((tid & 1) ? 4.0f : 2.0f);
        sphi[tid] = cI * phi * ((2.0f / NSQ) / 3.0f);
    }
    __syncthreads();

    {
        int k = tid + 1;
        float freq = (float)k * ((float)WK / (float)NGRID);
        float I = 0.0f;
#pragma unroll 4
        for (int i = 0; i <= NSQ; i++) {
            float z = -1.0f + (float)i * (2.0f / NSQ);
            I += sphi[i] * cospif(freq * z);
        }
        sq[k] = 2.0f / ((float)WK * I);
        if (tid == 0) {
            float I0 = 0.0f;
            for (int i = 0; i <= NSQ; i++) I0 += sphi[i];
            sq[0] = 2.0f / ((float)WK * I0);
        }
    }
    __syncthreads();

    for (int idx = tid; idx < HN * FN; idx += 256) {
        int f = idx & (FN - 1);
        int jm1 = idx >> 4;
        float q = sq[jm1 + 1];
        int src = (n * HN + (HN - 1 - jm1)) * FN + f;
        sA[idx] =  2.0f * q * fr[src];
        sB[idx] = -2.0f * q * fi[src];
    }
    __syncthreads();

    const int rl = tid & 31;
    const int jc = tid >> 5;
    const int r  = blockIdx.x * 32 + rl;
    {
        float xr = (float)(r - 2) * (1.0f / (float)NGRID);
        int jstart = jc * JCW + 1;
        float c0, s0, c1, s1;
        sincospif(2.0f * (float)jstart * xr, &s0, &c0);
        sincospif(2.0f * xr, &s1, &c1);
        unsigned long long cc = pk2(c0, c0), ss = pk2(s0, s0);
        unsigned long long C1 = pk2(c1, c1), S1 = pk2(s1, s1), nS1 = pk2(-s1, -s1);

        const ulonglong2* An = (const ulonglong2*)sA;
        const ulonglong2* Bn = (const ulonglong2*)sB;

        unsigned long long acc[8];
#pragma unroll
        for (int p = 0; p < 8; p++) acc[p] = 0ull;

        for (int jj = 0; jj < JCW; jj++) {
            int j0 = jc * JCW + jj;
            ulonglong2 a0 = An[4 * j0 + 0];
            ulonglong2 a1 = An[4 * j0 + 1];
            ulonglong2 a2 = An[4 * j0 + 2];
            ulonglong2 a3 = An[4 * j0 + 3];
            ulonglong2 b0 = Bn[4 * j0 + 0];
            ulonglong2 b1 = Bn[4 * j0 + 1];
            ulonglong2 b2 = Bn[4 * j0 + 2];
            ulonglong2 b3 = Bn[4 * j0 + 3];

            acc[0] = fma2(cc, a0.x, acc[0]);
            acc[1] = fma2(cc, a0.y, acc[1]);
            acc[2] = fma2(cc, a1.x, acc[2]);
            acc[3] = fma2(cc, a1.y, acc[3]);
            acc[4] = fma2(cc, a2.x, acc[4]);
            acc[5] = fma2(cc, a2.y, acc[5]);
            acc[6] = fma2(cc, a3.x, acc[6]);
            acc[7] = fma2(cc, a3.y, acc[7]);
            acc[0] = fma2(ss, b0.x, acc[0]);
            acc[1] = fma2(ss, b0.y, acc[1]);
            acc[2] = fma2(ss, b1.x, acc[2]);
            acc[3] = fma2(ss, b1.y, acc[3]);
            acc[4] = fma2(ss, b2.x, acc[4]);
            acc[5] = fma2(ss, b2.y, acc[5]);
            acc[6] = fma2(ss, b3.x, acc[6]);
            acc[7] = fma2(ss, b3.y, acc[7]);

            unsigned long long t0 = mul2(cc, C1);
            unsigned long long t1 = mul2(cc, S1);
            cc = fma2(ss, nS1, t0);
            ss = fma2(ss, C1,  t1);
        }

        float* pp = &part[(rl * NJC + jc) * FN];
#pragma unroll
        for (int p = 0; p < 8; p++) {
            float lo, hi;
            upk2(acc[p], lo, hi);
            pp[2 * p + 0] = lo;
            pp[2 * p + 1] = hi;
        }
    }
    __syncthreads();

    const float q0 = sq[0];
    for (int idx = tid; idx < 32 * FN; idx += 256) {
        int rl2 = idx >> 4;
        int f   = idx & (FN - 1);
        int rr  = blockIdx.x * 32 + rl2;
        if (rr < NPAD) {
            float v = q0;
#pragma unroll
            for (int q = 0; q < NJC; q++)
                v += part[(rl2 * NJC + q) * FN + f];
            g_tab[n][rr][f] = v;
        }
    }
}

// ---------------- kernel 2: fused lamprep + eval ----------------
// grid = 148, block = 512, 1 thread per sample (443 samples/block, tail-guarded).
#define TAB_FLOATS (NDIMS * NPAD * RSTR)                 // 46440
#define EV_LPART   TAB_FLOATS
#define EV_SC      (EV_LPART + NDIMS * TCOND * FN)
#define EV_LAM2    (EV_SC + NDIMS * FN)
#define EV_FLOATS  (EV_LAM2 + FN)
#define EV_SMEM_BYTES (EV_FLOATS * 4)

__global__ void __launch_bounds__(512, 1)
eval_kernel(const float* __restrict__ x,
            const float* __restrict__ lam,
            float* __restrict__ out) {
    extern __shared__ float sm[];
    float* tab   = sm;
    float* lpart = sm + EV_LPART;
    float* sc    = sm + EV_SC;
    float* sLam2 = sm + EV_LAM2;

    const int tid = threadIdx.x;

    // table broadcast L2 -> smem
    {
        const float4* src = (const float4*)&g_tab[0][0][0];
        float4* dst = (float4*)tab;
        for (int idx = tid; idx < TAB_FLOATS / 4; idx += 512)
            dst[idx] = src[idx];
    }
    __syncthreads();

    // --- fused lamprep stage 1: 300 interpolations on the t-grid ---
    if (tid < NDIMS * TCOND) {
        int n = tid / TCOND;
        int i = tid - n * TCOND;
        float t = 0.01f + 0.01f * (float)i;
        float xg = t * (float)NGRID;
        float fl = floorf(xg);
        float d  = xg - fl;
        int r0   = (int)fl;
        const float* rowp = tab + n * (NPAD * RSTR) + r0 * RSTR;
        float acc[FN];
#pragma unroll
        for (int f = 0; f < FN; f++) acc[f] = 0.0f;
#pragma unroll
        for (int tt = 0; tt < WK; tt++) {
            float z = (d + (float)(2 - tt)) * (1.0f / 3.0f);
            float wgt = es_w(z);
            const float4* p4 = (const float4*)(rowp + tt * RSTR);
#pragma unroll
            for (int cq = 0; cq < 4; cq++) {
                float4 v = p4[cq];
                acc[4 * cq + 0] = fmaf(wgt, v.x, acc[4 * cq + 0]);
                acc[4 * cq + 1] = fmaf(wgt, v.y, acc[4 * cq + 1]);
                acc[4 * cq + 2] = fmaf(wgt, v.z, acc[4 * cq + 2]);
                acc[4 * cq + 3] = fmaf(wgt, v.w, acc[4 * cq + 3]);
            }
        }
        float wt = (i == 0 || i == TCOND - 1) ? 0.005f : 0.01f;
#pragma unroll
        for (int f = 0; f < FN; f++)
            lpart[tid * FN + f] = wt * fmaxf(acc[f], 0.0f);
    }

    // --- main eval: 1 thread per sample, weights hoisted ---
    const int base = blockIdx.x * SPB;
    const int cnt  = min(SPB, MTOT - base);
    const bool active = (tid < cnt);
    const int m = base + (active ? tid : 0);

    const float xv0 = x[3 * m + 0];
    const float xv1 = x[3 * m + 1];
    const float xv2 = x[3 * m + 2];

    // hoist: row bases + all 18 packed weights before any gather
    int r0n[NDIMS];
    unsigned long long wb[NDIMS][WK];
#pragma unroll
    for (int n = 0; n < NDIMS; n++) {
        const float xn = (n == 0) ? xv0 : (n == 1) ? xv1 : xv2;
        float xg = xn * (float)NGRID;
        float fl = floorf(xg);
        float d  = xg - fl;
        r0n[n] = (int)fl;
#pragma unroll
        for (int t = 0; t < WK; t++) {
            float wgt = es_w((d + (float)(2 - t)) * (1.0f / 3.0f));
            wb[n][t] = pk2(wgt, wgt);
        }
    }

    unsigned long long prod[8];
#pragma unroll
    for (int n = 0; n < NDIMS; n++) {
        const float* rowp = tab + n * (NPAD * RSTR) + r0n[n] * RSTR;

        unsigned long long acc[8];
#pragma unroll
        for (int p = 0; p < 8; p++) acc[p] = 0ull;

#pragma unroll
        for (int t = 0; t < WK; t++) {
            unsigned long long w = wb[n][t];
            const ulonglong2* p4 = (const ulonglong2*)(rowp + t * RSTR);
            ulonglong2 v0 = p4[0];
            ulonglong2 v1 = p4[1];
            ulonglong2 v2 = p4[2];
            ulonglong2 v3 = p4[3];
            acc[0] = fma2(w, v0.x, acc[0]);
            acc[1] = fma2(w, v0.y, acc[1]);
            acc[2] = fma2(w, v1.x, acc[2]);
            acc[3] = fma2(w, v1.y, acc[3]);
            acc[4] = fma2(w, v2.x, acc[4]);
            acc[5] = fma2(w, v2.y, acc[5]);
            acc[6] = fma2(w, v3.x, acc[6]);
            acc[7] = fma2(w, v3.y, acc[7]);
        }

#pragma unroll
        for (int p = 0; p < 8; p++) {
            float lo, hi;
            upk2(acc[p], lo, hi);
            unsigned long long r = pk2(fmaxf(lo, 0.0f), fmaxf(hi, 0.0f));
            prod[p] = (n == 0) ? r : mul2(prod[p], r);
        }
    }

    __syncthreads();   // lpart complete

    // --- lamprep stage 2 ---
    if (tid < NDIMS * FN) {
        int nn = tid >> 4;
        int f  = tid & 15;
        float s = 0.0f;
        for (int q = 0; q < TCOND; q++)
            s += lpart[(nn * TCOND + q) * FN + f];
        sc[tid] = 1.0f / s;
    }
    __syncthreads();
    if (tid < FN)
        sLam2[tid] = lam[tid] * sc[tid] * sc[FN + tid] * sc[2 * FN + tid];
    __syncthreads();

    // --- dot with lam', write ---
    float s = 0.0f;
#pragma unroll
    for (int p = 0; p < 8; p++) {
        float lo, hi;
        upk2(prod[p], lo, hi);
        s = fmaf(lo, sLam2[2 * p + 0], s);
        s = fmaf(hi, sLam2[2 * p + 1], s);
    }
    if (active) out[m] = s;
}

// ---------------- launch ----------------
extern "C" void kernel_launch(void* const* d_in, const int* in_sizes, int n_in,
                              void* d_out, int out_size) {
    const float* x   = (const float*)d_in[0];
    const float* fr  = (const float*)d_in[1];
    const float* fi  = (const float*)d_in[2];
    const float* lam = (const float*)d_in[3];
    float* out = (float*)d_out;

    const int prep_smem = PREP_FLOATS * (int)sizeof(float);
    cudaFuncSetAttribute(prep_kernel,
                         cudaFuncAttributeMaxDynamicSharedMemorySize, prep_smem);
    prep_kernel<<<dim3((NPAD + 31) / 32, NDIMS), 256, prep_smem>>>(fr, fi);

    cudaFuncSetAttribute(eval_kernel,
                         cudaFuncAttributeMaxDynamicSharedMemorySize, EV_SMEM_BYTES);
    eval_kernel<<<NBLK, 512, EV_SMEM_BYTES>>>(x, lam, out);
}